// round 11
// baseline (speedup 1.0000x reference)
#include <cuda_runtime.h>
#include <cuda_bf16.h>

#define L_  1024
#define DM  1024
#define DI  2048
#define NS  16
#define DR  64
#define BB  2
#define CH  8
#define CT  (L_/CH)                 // 128 steps per chunk

typedef unsigned int        u32;
typedef unsigned short      u16;
typedef unsigned long long  u64;

// ---------------- scratch (static device globals; no allocation) -------------
__device__ float g_hid_t [BB*DI*L_];   // hidden, (b, d, t)
__device__ float g_gate_t[BB*DI*L_];   // gate,   (b, d, t)
__device__ float g_ssm   [BB*L_*96];   // (b*t, 96): [0:64)=dt_pre, [64:80)=B, [80:96)=C
__device__ float g_dt_t  [BB*DI*L_];   // softplus(dt), (b, d, t)
__device__ u16   g_x_hi  [BB*L_*DM];   // bf16 hi/lo splits, row-major (m, k)
__device__ u16   g_x_lo  [BB*L_*DM];
__device__ u16   g_win_hi[2*DI*DM];
__device__ u16   g_win_lo[2*DI*DM];
__device__ u16   g_wout_hi[DM*DI];
__device__ u16   g_wout_lo[DM*DI];
__device__ u16   g_so_hi [BB*L_*DI];   // scan output, (b, t, d) = (m, k)
__device__ u16   g_so_lo [BB*L_*DI];

__device__ __forceinline__ float softplusf(float x) {
    return x > 20.f ? x : log1pf(__expf(x));
}
__device__ __forceinline__ void split2(float v, u16& h, u16& l) {
    __nv_bfloat16 bh = __float2bfloat16_rn(v);
    float hf = __bfloat162float(bh);
    __nv_bfloat16 bl = __float2bfloat16_rn(v - hf);
    h = __bfloat16_as_ushort(bh);
    l = __bfloat16_as_ushort(bl);
}
__device__ __forceinline__ u32 smem_u32(const void* p) {
    u32 a;
    asm("{ .reg .u64 t; cvta.to.shared.u64 t, %1; cvt.u32.u64 %0, t; }" : "=r"(a) : "l"(p));
    return a;
}
__device__ __forceinline__ void ldm_x4(u32& r0, u32& r1, u32& r2, u32& r3, u32 addr) {
    asm volatile("ldmatrix.sync.aligned.m8n8.x4.shared.b16 {%0,%1,%2,%3}, [%4];"
                 : "=r"(r0), "=r"(r1), "=r"(r2), "=r"(r3) : "r"(addr));
}
__device__ __forceinline__ void mma_bf16(float* c, const u32* a, u32 b0, u32 b1) {
    asm volatile("mma.sync.aligned.m16n8k16.row.col.f32.bf16.bf16.f32 "
                 "{%0,%1,%2,%3}, {%4,%5,%6,%7}, {%8,%9}, {%0,%1,%2,%3};"
                 : "+f"(c[0]), "+f"(c[1]), "+f"(c[2]), "+f"(c[3])
                 : "r"(a[0]), "r"(a[1]), "r"(a[2]), "r"(a[3]), "r"(b0), "r"(b1));
}
__device__ __forceinline__ void cp16(u32 dst, const void* src) {
    asm volatile("cp.async.cg.shared.global [%0], [%1], 16;" :: "r"(dst), "l"(src));
}
__device__ __forceinline__ void cp_commit() {
    asm volatile("cp.async.commit_group;" ::: "memory");
}
template<int N>
__device__ __forceinline__ void cp_wait() {
    asm volatile("cp.async.wait_group %0;" :: "n"(N) : "memory");
}

// =============================================================================
//  bf16x3 split GEMM on mma.sync: CTA tile 128x128, BK=32, 8 warps (4x2),
//  warp tile 32x64.  C = Ah*Bh + Ah*Bl + Al*Bh  (fp32 accum; drop Al*Bl).
//  smem stage: Ah[128][40]bf16, Al, Bh, Bl; rows padded to 80B.
//  All stage fills are cp.async 16B from pre-split hi/lo global arrays.
// =============================================================================
#define ROWB    80
#define MATB    (128*ROWB)             // 10240 per matrix
#define STAGEB  (4*MATB)               // 40960: Ah, Al, Bh, Bl
#define DYN_SMEM (2*STAGEB)            // 81920

// EPI 0: in_proj (A=x, B=w_in) -> transposed split write hid/gate (b,d,t)
// EPI 1: out_proj (A=so, B=w_out) -> row-major Out
template<int EPI>
__global__ void __launch_bounds__(256, 2) gemm_mma(int Kfull, float* __restrict__ Out)
{
    const u16* Ah = (EPI == 0) ? g_x_hi   : g_so_hi;
    const u16* Al = (EPI == 0) ? g_x_lo   : g_so_lo;
    const u16* Bh = (EPI == 0) ? g_win_hi : g_wout_hi;
    const u16* Bl = (EPI == 0) ? g_win_lo : g_wout_lo;

    extern __shared__ __align__(16) char sm[];
    u32 smb = smem_u32(sm);

    int tid = threadIdx.x;
    int lane = tid & 31, wid = tid >> 5;
    int wm = wid >> 1, wn = wid & 1;
    int n0 = blockIdx.x * 128;
    int m0 = blockIdx.y * 128;

    float acc[2][8][4] = {};
    const int nch = Kfull / 32;

    // per-thread copy slots: 8 x 16B; li = tid + r*256, v = li>>2 (virtual row),
    // mat = v>>7, row = v&127, c4 = li&3
    const u16* srcs[4] = {Ah, Al, Bh, Bl};

    auto issue_stage = [&](int buf, int k0) {
        u32 dstb = smb + buf * STAGEB;
        #pragma unroll
        for (int r = 0; r < 8; r++) {
            int li  = tid + r * 256;
            int v   = li >> 2;
            int c4  = li & 3;
            int mat = v >> 7;
            int row = v & 127;
            int rb  = (mat < 2) ? m0 : n0;
            const u16* s = srcs[mat] + (size_t)(rb + row) * Kfull + k0 + c4 * 8;
            cp16(dstb + mat * MATB + row * ROWB + c4 * 16, s);
        }
    };

    issue_stage(0, 0);
    cp_commit();

    int rl = lane & 15, kh = lane >> 4;

    for (int i = 0; i < nch; i++) {
        if (i + 1 < nch) {
            issue_stage((i + 1) & 1, (i + 1) * 32);
            cp_commit();
            cp_wait<1>();
        } else {
            cp_wait<0>();
        }
        __syncthreads();

        u32 sb = smb + (i & 1) * STAGEB;
        #pragma unroll
        for (int kk = 0; kk < 2; kk++) {
            int kcolb = (kk * 16 + kh * 8) * 2;
            u32 ah[2][4], al[2][4];
            #pragma unroll
            for (int mi = 0; mi < 2; mi++) {
                u32 addr = sb + (u32)((wm * 32 + mi * 16 + rl) * ROWB + kcolb);
                ldm_x4(ah[mi][0], ah[mi][1], ah[mi][2], ah[mi][3], addr);
                ldm_x4(al[mi][0], al[mi][1], al[mi][2], al[mi][3], addr + MATB);
            }
            #pragma unroll
            for (int nj2 = 0; nj2 < 4; nj2++) {
                u32 addr = sb + 2 * MATB + (u32)((wn * 64 + nj2 * 16 + rl) * ROWB + kcolb);
                u32 bh[4], bl[4];
                ldm_x4(bh[0], bh[1], bh[2], bh[3], addr);
                ldm_x4(bl[0], bl[1], bl[2], bl[3], addr + MATB);
                #pragma unroll
                for (int mi = 0; mi < 2; mi++) {
                    #pragma unroll
                    for (int o = 0; o < 2; o++) {
                        float* c = acc[mi][nj2 * 2 + o];
                        mma_bf16(c, ah[mi], bh[o], bh[o + 2]);
                        mma_bf16(c, ah[mi], bl[o], bl[o + 2]);
                        mma_bf16(c, al[mi], bh[o], bh[o + 2]);
                    }
                }
            }
        }
        __syncthreads();
    }

    // ---- epilogue: stage C (128x132 fp32) in smem, coalesced write-out ----
    float* Cs = (float*)sm;
    {
        int tq = lane >> 2, tr2 = (lane & 3) * 2;
        #pragma unroll
        for (int mi = 0; mi < 2; mi++) {
            #pragma unroll
            for (int nj = 0; nj < 8; nj++) {
                int row = wm * 32 + mi * 16 + tq;
                int col = wn * 64 + nj * 8 + tr2;
                float* c = acc[mi][nj];
                *(float2*)&Cs[row * 132 + col]       = make_float2(c[0], c[1]);
                *(float2*)&Cs[(row + 8) * 132 + col] = make_float2(c[2], c[3]);
            }
        }
    }
    __syncthreads();

    if (EPI == 0) {
        int bb = m0 >> 10;
        int t0 = m0 & 1023;
        float* dst = (n0 < DI) ? g_hid_t : g_gate_t;
        int nb = n0 & (DI - 1);
        #pragma unroll
        for (int r = 0; r < 16; r++) {
            int li = tid + r * 256;
            int col = li & 127, mb = li >> 7;
            float4 v = make_float4(Cs[(mb * 4 + 0) * 132 + col],
                                   Cs[(mb * 4 + 1) * 132 + col],
                                   Cs[(mb * 4 + 2) * 132 + col],
                                   Cs[(mb * 4 + 3) * 132 + col]);
            *(float4*)&dst[((size_t)bb * DI + nb + col) * L_ + t0 + mb * 4] = v;
        }
    } else {
        #pragma unroll
        for (int r = 0; r < 16; r++) {
            int li = tid + r * 256;
            int row = li >> 5, cb = li & 31;
            float4 v = *(float4*)&Cs[row * 132 + cb * 4];
            *(float4*)&Out[(size_t)(m0 + row) * DM + n0 + cb * 4] = v;
        }
    }
}

// ---------------- fp32 -> split bf16 hi/lo converter -------------------------
template<int DST>
__global__ void cvt_pack(const float* __restrict__ in, int n4)
{
    u16* oh = (DST == 0) ? g_x_hi : (DST == 1) ? g_win_hi : g_wout_hi;
    u16* ol = (DST == 0) ? g_x_lo : (DST == 1) ? g_win_lo : g_wout_lo;
    int i = blockIdx.x * blockDim.x + threadIdx.x;
    if (i < n4) {
        float4 v = ((const float4*)in)[i];
        ushort4 h, l;
        split2(v.x, h.x, l.x); split2(v.y, h.y, l.y);
        split2(v.z, h.z, l.z); split2(v.w, h.w, l.w);
        ((ushort4*)oh)[i] = h;
        ((ushort4*)ol)[i] = l;
    }
}

// =============================================================================
//  Small GEMM (64x64, 4x4 micro) for x_proj / dt_proj  (FFMA)
// =============================================================================
template<int EPI, bool AKMAJ, int ASRC>
__global__ __launch_bounds__(256)
void gemm_k(const float* __restrict__ W, int M, int N, int K, int lda,
            const float* __restrict__ bias)
{
    const float* A = (ASRC == 1) ? g_hid_t : g_ssm;

    __shared__ __align__(16) float As[16][68];
    __shared__ __align__(16) float Bs[16][68];

    int tid = threadIdx.x;
    int n0 = blockIdx.x * 64;
    int m0 = blockIdx.y * 64;
    int tr = tid >> 4;
    int tc = tid & 15;
    float acc[4][4] = {};

    for (int k0 = 0; k0 < K; k0 += 16) {
        if (AKMAJ) {
            #pragma unroll
            for (int i = 0; i < 4; i++) {
                int li = tid + i * 256;
                int m = li & 63, k = li >> 6;
                int gm = m0 + m;
                As[k][m] = A[(((gm >> 10) * K) + k0 + k) * L_ + (gm & 1023)];
            }
        } else {
            #pragma unroll
            for (int i = 0; i < 4; i++) {
                int li = tid + i * 256;
                int k = li & 15, m = li >> 4;
                As[k][m] = A[(m0 + m) * lda + k0 + k];
            }
        }
        #pragma unroll
        for (int i = 0; i < 4; i++) {
            int li = tid + i * 256;
            int k = li & 15, n = li >> 4;
            int gn = n0 + n;
            Bs[k][n] = (gn < N) ? W[gn * K + k0 + k] : 0.f;
        }
        __syncthreads();
        #pragma unroll
        for (int k = 0; k < 16; k++) {
            float4 av = *(const float4*)&As[k][tr * 4];
            float4 bv = *(const float4*)&Bs[k][tc * 4];
            float a4[4] = {av.x, av.y, av.z, av.w};
            float b4[4] = {bv.x, bv.y, bv.z, bv.w};
            #pragma unroll
            for (int i = 0; i < 4; i++)
                #pragma unroll
                for (int j = 0; j < 4; j++)
                    acc[i][j] = fmaf(a4[i], b4[j], acc[i][j]);
        }
        __syncthreads();
    }

    if (EPI == 1) {
        #pragma unroll
        for (int i = 0; i < 4; i++) {
            int gm = m0 + tr * 4 + i;
            #pragma unroll
            for (int j = 0; j < 4; j++) {
                int gn = n0 + tc * 4 + j;
                if (gn < N) g_ssm[gm * 96 + gn] = acc[i][j];
            }
        }
    } else {
        int bb = m0 >> 10;
        int t0 = (m0 & 1023) + tr * 4;
        #pragma unroll
        for (int j = 0; j < 4; j++) {
            int gn = n0 + tc * 4 + j;
            float bz = bias[gn];
            float4 v;
            v.x = softplusf(acc[0][j] + bz);
            v.y = softplusf(acc[1][j] + bz);
            v.z = softplusf(acc[2][j] + bz);
            v.w = softplusf(acc[3][j] + bz);
            *(float4*)&g_dt_t[((size_t)bb * DI + gn) * L_ + t0] = v;
        }
    }
}

// =============================================================================
//  Fused chunked bidirectional scan (epilogue writes split so (b,t,d))
// =============================================================================
__global__ __launch_bounds__(256)
void scan_fused(const float* __restrict__ A_log, const float* __restrict__ Dp)
{
    __shared__ float sP  [2][NS][CH];
    __shared__ float sS  [2][NS][CH];
    __shared__ float sCin[2][NS][CH];
    __shared__ float y0[L_];   // fwd contributions
    __shared__ float y1[L_];   // bwd contributions

    int bd   = blockIdx.x;
    int b    = bd >> 11;
    int d    = bd & (DI - 1);
    int c    = threadIdx.x >> 5;          // chunk
    int lane = threadIdx.x & 31;
    int n    = lane & 15;
    bool fw  = lane < 16;
    int dir  = fw ? 0 : 1;

    size_t off = ((size_t)b * DI + d) * L_;
    const float* dtp = g_dt_t  + off;
    const float* hp  = g_hid_t + off;
    const float* ssm = g_ssm   + (size_t)b * L_ * 96;
    float An = -__expf(A_log[d * NS + n]);

    int lo = c * CT, hi = lo + CT - 1;
    int sdelta = fw ? 96 : -96;

    // -------- phase A: chunk operator (P, S) --------
    {
        float s = 0.f, P = 1.f;
        float pb = (hi + 1 < L_) ? __expf(An * dtp[hi + 1]) : 0.f;
        const float* sp = ssm + (fw ? lo : hi) * 96 + 64 + n;
        for (int i0 = 0; i0 < CT; i0 += 4) {
            int tb = fw ? lo + i0 : hi - i0 - 3;
            float4 dt4 = *(const float4*)&dtp[tb];
            float4 h4  = *(const float4*)&hp[tb];
            float dts[4] = {dt4.x, dt4.y, dt4.z, dt4.w};
            float hs4[4] = {h4.x, h4.y, h4.z, h4.w};
            #pragma unroll
            for (int j = 0; j < 4; j++) {
                int jj = fw ? j : 3 - j;
                float dtv = dts[jj], h = hs4[jj];
                float a  = __expf(An * dtv);
                float Bv = sp[0];
                float u  = dtv * Bv * h;
                float coef = fw ? a : pb;
                s = fmaf(coef, s, u);
                P *= coef;
                pb = a;
                sp += sdelta;
            }
        }
        sP[dir][n][c] = P;
        sS[dir][n][c] = s;
    }
    __syncthreads();

    // -------- combine: 32 threads, one (dir, n) chain each --------
    if (threadIdx.x < 32) {
        int dr = threadIdx.x >> 4, nn = threadIdx.x & 15;
        float cin = 0.f;
        if (dr == 0) {
            #pragma unroll
            for (int cc = 0; cc < CH; cc++) {
                sCin[0][nn][cc] = cin;
                cin = fmaf(sP[0][nn][cc], cin, sS[0][nn][cc]);
            }
        } else {
            #pragma unroll
            for (int cc = CH - 1; cc >= 0; cc--) {
                sCin[1][nn][cc] = cin;
                cin = fmaf(sP[1][nn][cc], cin, sS[1][nn][cc]);
            }
        }
    }
    __syncthreads();

    // -------- phase C: seeded re-scan + multi-value shuffle reduction --------
    {
        float s  = sCin[dir][n][c];
        float pb = (hi + 1 < L_) ? __expf(An * dtp[hi + 1]) : 0.f;
        const float* sp = ssm + (fw ? lo : hi) * 96 + 64 + n;
        float* yarr = fw ? y0 : y1;
        int vsel = n >> 2;
        int psel = n & 3;
        for (int i0 = 0; i0 < CT; i0 += 4) {
            int tb = fw ? lo + i0 : hi - i0 - 3;
            float4 dt4 = *(const float4*)&dtp[tb];
            float4 h4  = *(const float4*)&hp[tb];
            float dts[4] = {dt4.x, dt4.y, dt4.z, dt4.w};
            float hs4[4] = {h4.x, h4.y, h4.z, h4.w};
            float v[4];
            #pragma unroll
            for (int j = 0; j < 4; j++) {
                int jj = fw ? j : 3 - j;
                float dtv = dts[jj], h = hs4[jj];
                float a  = __expf(An * dtv);
                float Bv = sp[0];
                float Cv = sp[16];
                float u  = dtv * Bv * h;
                float coef = fw ? a : pb;
                s = fmaf(coef, s, u);
                float base = fw ? s : (s - u);
                v[jj] = Cv * base;
                pb = a;
                sp += sdelta;
            }
            #pragma unroll
            for (int i = 0; i < 4; i++) {
                v[i] += __shfl_xor_sync(0xffffffffu, v[i], 8);
                v[i] += __shfl_xor_sync(0xffffffffu, v[i], 4);
            }
            float w = (vsel == 0) ? v[0] : (vsel == 1) ? v[1] : (vsel == 2) ? v[2] : v[3];
            w += __shfl_xor_sync(0xffffffffu, w, 2);
            w += __shfl_xor_sync(0xffffffffu, w, 1);
            if (psel == 0) yarr[tb + vsel] = w;
        }
    }
    __syncthreads();

    // -------- epilogue: gating -> split bf16 so, (b, t, d) layout ------------
    {
        float Dv = Dp[d];
        int t4 = threadIdx.x * 4;
        float4 g4 = *(const float4*)&g_gate_t[off + t4];
        float4 h4 = *(const float4*)&hp[t4];
        float4 ya = *(const float4*)&y0[t4];
        float4 yb = *(const float4*)&y1[t4];
        float o[4];
        o[0] = (1.3f * (ya.x + yb.x) + h4.x * Dv) * (g4.x / (1.f + __expf(-g4.x)));
        o[1] = (1.3f * (ya.y + yb.y) + h4.y * Dv) * (g4.y / (1.f + __expf(-g4.y)));
        o[2] = (1.3f * (ya.z + yb.z) + h4.z * Dv) * (g4.z / (1.f + __expf(-g4.z)));
        o[3] = (1.3f * (ya.w + yb.w) + h4.w * Dv) * (g4.w / (1.f + __expf(-g4.w)));
        size_t base = (size_t)b * L_ * DI + d;
        #pragma unroll
        for (int j = 0; j < 4; j++) {
            u16 hbits, lbits;
            split2(o[j], hbits, lbits);
            g_so_hi[base + (size_t)(t4 + j) * DI] = hbits;
            g_so_lo[base + (size_t)(t4 + j) * DI] = lbits;
        }
    }
}

// ---------------- launch -----------------------------------------------------
extern "C" void kernel_launch(void* const* d_in, const int* in_sizes, int n_in,
                              void* d_out, int out_size)
{
    const float* x      = (const float*)d_in[0];  // (2,1024,1024)
    const float* w_in   = (const float*)d_in[1];  // (4096,1024)
    const float* w_x    = (const float*)d_in[2];  // (96,2048)
    const float* w_dt   = (const float*)d_in[3];  // (2048,64)
    const float* b_dt   = (const float*)d_in[4];  // (2048,)
    const float* A_log  = (const float*)d_in[5];  // (2048,16)
    const float* Dvec   = (const float*)d_in[6];  // (2048,)
    const float* w_out  = (const float*)d_in[7];  // (1024,2048)
    float* out = (float*)d_out;                   // (2,1024,1024)

    const int M = BB * L_;  // 2048

    cudaFuncSetAttribute(gemm_mma<0>, cudaFuncAttributeMaxDynamicSharedMemorySize, DYN_SMEM);
    cudaFuncSetAttribute(gemm_mma<1>, cudaFuncAttributeMaxDynamicSharedMemorySize, DYN_SMEM);

    // 0) split inputs to bf16 hi/lo
    cvt_pack<0><<<(BB*L_*DM/4 + 255)/256, 256>>>(x,     BB*L_*DM/4);
    cvt_pack<1><<<(2*DI*DM/4  + 255)/256, 256>>>(w_in,  2*DI*DM/4);
    cvt_pack<2><<<(DM*DI/4    + 255)/256, 256>>>(w_out, DM*DI/4);

    // 1) in_proj (mma.sync bf16x3, cp.async) -> hid/gate (b,d,t)
    gemm_mma<0><<<dim3(2*DI/128, M/128), 256, DYN_SMEM>>>(DM, nullptr);
    // 2) x_proj: hidden (K-major) @ (96x2048)^T -> g_ssm
    gemm_k<1, true, 1><<<dim3(2, M/64), 256>>>(w_x, M, 96, DI, 0, nullptr);
    // 3) dt_proj: ssm[:, :64] @ (2048x64)^T + b, softplus -> g_dt_t
    gemm_k<2, false, 2><<<dim3(DI/64, M/64), 256>>>(w_dt, M, DI, DR, 96, b_dt);
    // 4) fused chunked bidirectional scan (writes split so)
    scan_fused<<<BB * DI, 256>>>(A_log, Dvec);
    // 5) out_proj (mma.sync bf16x3, cp.async)
    gemm_mma<1><<<dim3(DM/128, M/128), 256, DYN_SMEM>>>(DI, out);
}